// round 13
// baseline (speedup 1.0000x reference)
#include <cuda_runtime.h>
#include <math.h>

#define BB 128
#define CC 128
#define TN 2000
#define FF 64
#define HH 128
#define SEQN 10

typedef unsigned long long ull;

// ---- packed f32x2 helpers (sm_103a) -----------------------------------------
__device__ __forceinline__ ull d2(float x) {
    ull r; asm("mov.b64 %0, {%1, %1};" : "=l"(r) : "f"(x)); return r;
}
__device__ __forceinline__ ull pk2(float a, float b) {
    ull r; asm("mov.b64 %0, {%1, %2};" : "=l"(r) : "f"(a), "f"(b)); return r;
}
__device__ __forceinline__ void up2(ull v, float& a, float& b) {
    asm("mov.b64 {%0, %1}, %2;" : "=f"(a), "=f"(b) : "l"(v));
}
__device__ __forceinline__ void fma2(ull& d, ull a, ull b) {
    asm("fma.rn.f32x2 %0, %1, %2, %0;" : "+l"(d) : "l"(a), "l"(b));
}
__device__ __forceinline__ ull mul2(ull a, ull b) {
    ull r; asm("mul.rn.f32x2 %0, %1, %2;" : "=l"(r) : "l"(a), "l"(b)); return r;
}

// ---------------- scratch (device globals; no runtime allocation) -------------
__device__ float g_Ms[BB*CC*CC];     // M = I - cov/c (symmetric)
__device__ float g_cpar[BB*2];       // {invc, logc} per batch
__device__ float g_adj[BB*CC*CC];
__device__ float g_res[BB*TN*FF];
__device__ float g_p0[BB*TN*FF];     // conv1 partial (channels 0..63)
__device__ float g_p1[BB*TN*FF];     // conv1 partial (channels 64..127)
__device__ float g_t1[BB*TN*FF];
__device__ float g_t2[BB*TN*FF];
__device__ float g_tcn[BB*TN*FF];
__device__ float g_nf[2*BB*CC*FF];
__device__ float g_geo[BB*CC*FF];
__device__ float g_dpart[4*BB*HH];
__device__ float g_seqin[BB*SEQN*HH];
__device__ float g_spksum;

// ---------------- tiny kernel to anchor the fork event -----------------------
__global__ void k_zero() {
    if (threadIdx.x == 0) g_spksum = 0.0f;
}

// ---------------- cov + mean + trace + M: one CTA per batch ------------------
// Row means are accumulated during the Gram load, so no separate k_mean.
__global__ void __launch_bounds__(256, 1) k_cov(const float* __restrict__ X) {
    __shared__ float Xs[32 * 130];
    __shared__ float mn[128];
    __shared__ float red[256];
    __shared__ float csh[2];
    int b = blockIdx.x, tid = threadIdx.x;
    const float* Xb = X + (size_t)b * CC * TN;

    int ty = tid >> 4, tx = tid & 15;
    int r0 = ty * 8, c0 = tx * 8;
    int kkl = tid & 31, iw = tid >> 5;   // lane, warp

    float rsum[16];
    #pragma unroll
    for (int j = 0; j < 16; j++) rsum[j] = 0.f;

    ull acc[8][4];
    #pragma unroll
    for (int i = 0; i < 8; i++)
        #pragma unroll
        for (int jj = 0; jj < 4; jj++) acc[i][jj] = 0ull;

    for (int k0 = 0; k0 < TN; k0 += 32) {
        int k = k0 + kkl;
        bool ok = (k < TN);
        #pragma unroll 4
        for (int j = 0; j < 16; j++) {
            int i = iw + 8 * j;
            float v = ok ? Xb[(size_t)i * TN + k] : 0.f;
            Xs[kkl * 130 + i] = v;
            rsum[j] += v;
        }
        __syncthreads();
        #pragma unroll 4
        for (int kk = 0; kk < 32; kk++) {
            const float* row = &Xs[kk * 130];
            const ull* ap = reinterpret_cast<const ull*>(row + r0);
            const ull* bp = reinterpret_cast<const ull*>(row + c0);
            ull b0 = bp[0], b1 = bp[1], b2 = bp[2], b3 = bp[3];
            float a8[8];
            up2(ap[0], a8[0], a8[1]); up2(ap[1], a8[2], a8[3]);
            up2(ap[2], a8[4], a8[5]); up2(ap[3], a8[6], a8[7]);
            #pragma unroll
            for (int i = 0; i < 8; i++) {
                ull ad = d2(a8[i]);
                fma2(acc[i][0], ad, b0);
                fma2(acc[i][1], ad, b1);
                fma2(acc[i][2], ad, b2);
                fma2(acc[i][3], ad, b3);
            }
        }
        __syncthreads();
    }

    #pragma unroll
    for (int j = 0; j < 16; j++) {
        float s = rsum[j];
        #pragma unroll
        for (int o = 16; o; o >>= 1) s += __shfl_xor_sync(0xffffffffu, s, o);
        if (kkl == 0) mn[iw + 8 * j] = s * (1.0f / TN);
    }
    __syncthreads();

    float dsum = 0.f;
    if (ty == tx) {
        #pragma unroll
        for (int i = 0; i < 8; i++) {
            float lo, hi;
            up2(acc[i][i >> 1], lo, hi);
            float raw = (i & 1) ? hi : lo;
            float mi = mn[r0 + i];
            dsum += (raw - (float)TN * mi * mi) * (1.0f / (TN - 1)) + 1e-4f;
        }
    }
    red[tid] = dsum;
    __syncthreads();
    for (int o = 128; o; o >>= 1) {
        if (tid < o) red[tid] += red[tid + o];
        __syncthreads();
    }
    if (tid == 0) {
        float c = 1.06f * red[0] * (1.0f / 128.0f);
        csh[0] = 1.0f / c;
        csh[1] = logf(c);
        g_cpar[b * 2 + 0] = csh[0];
        g_cpar[b * 2 + 1] = csh[1];
    }
    __syncthreads();
    float invc = csh[0];

    float* Mb = g_Ms + (size_t)b * CC * CC;
    #pragma unroll
    for (int i = 0; i < 8; i++) {
        int gi = r0 + i;
        float mi = mn[gi];
        float v8[8];
        #pragma unroll
        for (int jj = 0; jj < 4; jj++) up2(acc[i][jj], v8[2 * jj], v8[2 * jj + 1]);
        #pragma unroll
        for (int j = 0; j < 8; j++) {
            int gj = c0 + j;
            float v = (v8[j] - (float)TN * mi * mn[gj]) * (1.0f / (TN - 1));
            if (gi == gj) v += 1e-4f;
            v8[j] = ((gi == gj) ? 1.0f : 0.0f) - v * invc;
        }
        float* op = Mb + (size_t)gi * CC + c0;
        *reinterpret_cast<float4*>(op) = make_float4(v8[0], v8[1], v8[2], v8[3]);
        *reinterpret_cast<float4*>(op + 4) = make_float4(v8[4], v8[5], v8[6], v8[7]);
    }
}

// ---------------- matrix log via Paterson-Stockmeyer (5 matmuls) -------------
__global__ void __launch_bounds__(256, 1) k_logadj() {
    extern __shared__ float sm[];
    float* Ps = sm;            // holds M initially, then P
    float* Ws = sm + 16384;    // W = M^2
    int b = blockIdx.x, tid = threadIdx.x;
    const float* Mb = g_Ms + (size_t)b * CC * CC;
    float logc = g_cpar[b * 2 + 1];

    for (int idx = tid; idx < 4096; idx += 256)
        reinterpret_cast<float4*>(Ps)[idx] = __ldg(reinterpret_cast<const float4*>(Mb) + idx);
    __syncthreads();

    int ty = tid >> 4, tx = tid & 15;
    int r0 = ty * 8, c0 = tx * 8;

    ull Mt2[8][4];
    #pragma unroll
    for (int i = 0; i < 8; i++) {
        const ull* mp = reinterpret_cast<const ull*>(&Ps[(r0 + i) * 128 + c0]);
        #pragma unroll
        for (int jj = 0; jj < 4; jj++) Mt2[i][jj] = mp[jj];
    }

    // ---- W = M^2 ----
    {
        ull acc[8][4];
        #pragma unroll
        for (int i = 0; i < 8; i++)
            #pragma unroll
            for (int jj = 0; jj < 4; jj++) acc[i][jj] = 0ull;
        #pragma unroll 2
        for (int kk = 0; kk < 128; kk++) {
            float4 p0 = *reinterpret_cast<const float4*>(&Ps[kk * 128 + r0]);
            float4 p1 = *reinterpret_cast<const float4*>(&Ps[kk * 128 + r0 + 4]);
            const ull* mp = reinterpret_cast<const ull*>(&Ps[kk * 128 + c0]);
            ull m0 = mp[0], m1 = mp[1], m2 = mp[2], m3 = mp[3];
            ull pd[8] = {d2(p0.x), d2(p0.y), d2(p0.z), d2(p0.w),
                         d2(p1.x), d2(p1.y), d2(p1.z), d2(p1.w)};
            #pragma unroll
            for (int i = 0; i < 8; i++) {
                fma2(acc[i][0], pd[i], m0);
                fma2(acc[i][1], pd[i], m1);
                fma2(acc[i][2], pd[i], m2);
                fma2(acc[i][3], pd[i], m3);
            }
        }
        #pragma unroll
        for (int i = 0; i < 8; i++) {
            ull* wp = reinterpret_cast<ull*>(&Ws[(r0 + i) * 128 + c0]);
            #pragma unroll
            for (int jj = 0; jj < 4; jj++) wp[jj] = acc[i][jj];
        }
        __syncthreads();
    }

    // ---- init P = W/10 + I/8 + M/9 ----
    {
        ull c10 = d2(0.1f), c9 = d2(1.0f / 9.0f);
        #pragma unroll
        for (int i = 0; i < 8; i++) {
            const ull* wp = reinterpret_cast<const ull*>(&Ws[(r0 + i) * 128 + c0]);
            ull* pp = reinterpret_cast<ull*>(&Ps[(r0 + i) * 128 + c0]);
            #pragma unroll
            for (int jj = 0; jj < 4; jj++) {
                ull v = mul2(wp[jj], c10);
                fma2(v, Mt2[i][jj], c9);
                float lo, hi;
                up2(v, lo, hi);
                int gi = r0 + i;
                if (gi == c0 + 2 * jj)     lo += 0.125f;
                if (gi == c0 + 2 * jj + 1) hi += 0.125f;
                pp[jj] = pk2(lo, hi);
            }
        }
        __syncthreads();
    }

    const float aj[4] = {1.0f / 6.0f, 0.25f, 0.5f, 0.0f};
    const float bj[4] = {1.0f / 7.0f, 0.2f, 1.0f / 3.0f, 1.0f};

    ull acc[8][4];
    for (int step = 0; step < 4; step++) {
        #pragma unroll
        for (int i = 0; i < 8; i++)
            #pragma unroll
            for (int jj = 0; jj < 4; jj++) acc[i][jj] = 0ull;

        #pragma unroll 2
        for (int kk = 0; kk < 128; kk++) {
            float4 p0 = *reinterpret_cast<const float4*>(&Ps[kk * 128 + r0]);
            float4 p1 = *reinterpret_cast<const float4*>(&Ps[kk * 128 + r0 + 4]);
            const ull* wp = reinterpret_cast<const ull*>(&Ws[kk * 128 + c0]);
            ull w0 = wp[0], w1 = wp[1], w2 = wp[2], w3 = wp[3];
            ull pd[8] = {d2(p0.x), d2(p0.y), d2(p0.z), d2(p0.w),
                         d2(p1.x), d2(p1.y), d2(p1.z), d2(p1.w)};
            #pragma unroll
            for (int i = 0; i < 8; i++) {
                fma2(acc[i][0], pd[i], w0);
                fma2(acc[i][1], pd[i], w1);
                fma2(acc[i][2], pd[i], w2);
                fma2(acc[i][3], pd[i], w3);
            }
        }

        ull bjd = d2(bj[step]);
        #pragma unroll
        for (int i = 0; i < 8; i++)
            #pragma unroll
            for (int jj = 0; jj < 4; jj++) fma2(acc[i][jj], Mt2[i][jj], bjd);

        if (step < 3) {
            float av = aj[step];
            __syncthreads();
            #pragma unroll
            for (int i = 0; i < 8; i++) {
                ull* pp = reinterpret_cast<ull*>(&Ps[(r0 + i) * 128 + c0]);
                int gi = r0 + i;
                #pragma unroll
                for (int jj = 0; jj < 4; jj++) {
                    ull v = acc[i][jj];
                    if (gi == c0 + 2 * jj || gi == c0 + 2 * jj + 1) {
                        float lo, hi;
                        up2(v, lo, hi);
                        if (gi == c0 + 2 * jj)     lo += av;
                        else                        hi += av;
                        v = pk2(lo, hi);
                    }
                    pp[jj] = v;
                }
            }
            __syncthreads();
        }
    }

    #pragma unroll
    for (int i = 0; i < 8; i++) {
        float La[8];
        #pragma unroll
        for (int jj = 0; jj < 4; jj++) {
            float lo, hi;
            up2(acc[i][jj], lo, hi);
            La[2 * jj] = -lo;
            La[2 * jj + 1] = -hi;
        }
        int dj = (r0 + i) - c0;
        if (dj >= 0 && dj < 8) La[dj] += logc;

        float mx = -1e30f;
        #pragma unroll
        for (int j = 0; j < 8; j++) mx = fmaxf(mx, La[j]);
        #pragma unroll
        for (int o = 1; o < 16; o <<= 1) mx = fmaxf(mx, __shfl_xor_sync(0xffffffffu, mx, o));
        float e[8], s = 0.f;
        #pragma unroll
        for (int j = 0; j < 8; j++) { e[j] = expf(La[j] - mx); s += e[j]; }
        #pragma unroll
        for (int o = 1; o < 16; o <<= 1) s += __shfl_xor_sync(0xffffffffu, s, o);
        float inv = 1.0f / s;
        float* outp = g_adj + ((size_t)b * 128 + r0 + i) * 128 + c0;
        *reinterpret_cast<float4*>(outp) =
            make_float4(e[0] * inv, e[1] * inv, e[2] * inv, e[3] * inv);
        *reinterpret_cast<float4*>(outp + 4) =
            make_float4(e[4] * inv, e[5] * inv, e[6] * inv, e[7] * inv);
    }
}

// ---------------- res GEMM: g_res = X_t @ rw + rb ----------------------------
__global__ void __launch_bounds__(256, 3)
k_res(const float* __restrict__ X, const float* __restrict__ rw,
      const float* __restrict__ rb) {
    extern __shared__ float sm[];
    float* Xs = sm;               // 128 c x 132
    int b = blockIdx.y;
    int t0 = blockIdx.x * 128;
    int tid = threadIdx.x;
    int warp = tid >> 5, lane = tid & 31;
    const float* Xb = X + (size_t)b * CC * TN;

    for (int c = warp; c < 128; c += 8) {
        const float* src = Xb + (size_t)c * TN + t0;
        int u = lane * 4;
        float4 v;
        if (t0 + u + 3 < TN) {
            v = *reinterpret_cast<const float4*>(src + u);
        } else {
            v.x = (t0 + u     < TN) ? src[u]     : 0.f;
            v.y = (t0 + u + 1 < TN) ? src[u + 1] : 0.f;
            v.z = (t0 + u + 2 < TN) ? src[u + 2] : 0.f;
            v.w = 0.f;
        }
        *reinterpret_cast<float4*>(&Xs[c * 132 + u]) = v;
    }
    __syncthreads();

    int tg = tid >> 3, fg = tid & 7;
    int f0 = fg * 8, u0 = tg * 4;

    ull acc[4][4];
    #pragma unroll
    for (int jj = 0; jj < 4; jj++) {
        ull bj = pk2(rb[f0 + 2 * jj], rb[f0 + 2 * jj + 1]);
        #pragma unroll
        for (int i = 0; i < 4; i++) acc[i][jj] = bj;
    }

    #pragma unroll 4
    for (int c = 0; c < 128; c++) {
        ull xd[4];
        #pragma unroll
        for (int s = 0; s < 4; s++) xd[s] = d2(Xs[c * 132 + u0 + s]);
        const ull* rp = reinterpret_cast<const ull*>(rw + c * 64 + f0);
        #pragma unroll
        for (int jj = 0; jj < 4; jj++) {
            ull wv = __ldg(rp + jj);
            #pragma unroll
            for (int i = 0; i < 4; i++) fma2(acc[i][jj], xd[i], wv);
        }
    }

    #pragma unroll
    for (int i = 0; i < 4; i++) {
        int t = t0 + u0 + i;
        if (t < TN) {
            float v8[8];
            #pragma unroll
            for (int jj = 0; jj < 4; jj++) up2(acc[i][jj], v8[2 * jj], v8[2 * jj + 1]);
            float* op = g_res + ((size_t)b * TN + t) * 64 + f0;
            *reinterpret_cast<float4*>(op) = make_float4(v8[0], v8[1], v8[2], v8[3]);
            *reinterpret_cast<float4*>(op + 4) = make_float4(v8[4], v8[5], v8[6], v8[7]);
        }
    }
}

// ---------------- conv1 partial GEMM: 64 channels per CTA, 2 CTAs/SM ---------
__global__ void __launch_bounds__(256, 2)
k_conv1g(const float* __restrict__ X, const float* __restrict__ w1,
         float* __restrict__ p0, float* __restrict__ p1) {
    extern __shared__ float sm[];
    float* Xs = sm;                 // 64 x 130
    float* Ws = sm + 64 * 130;      // 3*64*64
    int b = blockIdx.y;
    int t0 = blockIdx.x * 128;
    int half = blockIdx.z;
    int tid = threadIdx.x;
    int warp = tid >> 5, lane = tid & 31;
    const float* Xb = X + ((size_t)b * CC + half * 64) * TN;
    float* outp = half ? p1 : p0;

    for (int c = warp; c < 64; c += 8) {
        const float* src = Xb + (size_t)c * TN;
        for (int u = lane; u < 130; u += 32) {
            int t = t0 - 1 + u;
            Xs[c * 130 + u] = (t >= 0 && t < TN) ? src[t] : 0.f;
        }
    }
    for (int idx = tid; idx < 3 * 64 * 64; idx += 256) {
        int tap = idx >> 12, rem = idx & 4095;
        Ws[idx] = w1[tap * 8192 + half * 4096 + rem];
    }
    __syncthreads();

    int tg = tid >> 3, fg = tid & 7;
    int f0 = fg * 8, u0 = tg * 4;

    ull acc[4][4];
    #pragma unroll
    for (int i = 0; i < 4; i++)
        #pragma unroll
        for (int jj = 0; jj < 4; jj++) acc[i][jj] = 0ull;

    #pragma unroll 2
    for (int c = 0; c < 64; c++) {
        ull xd[6];
        #pragma unroll
        for (int s = 0; s < 6; s++) xd[s] = d2(Xs[c * 130 + u0 + s]);
        #pragma unroll
        for (int tap = 0; tap < 3; tap++) {
            const ull* wp = reinterpret_cast<const ull*>(&Ws[tap * 4096 + c * 64 + f0]);
            #pragma unroll
            for (int jj = 0; jj < 4; jj++) {
                ull wv = wp[jj];
                #pragma unroll
                for (int i = 0; i < 4; i++) fma2(acc[i][jj], xd[i + tap], wv);
            }
        }
    }

    #pragma unroll
    for (int i = 0; i < 4; i++) {
        int t = t0 + u0 + i;
        if (t < TN) {
            float v8[8];
            #pragma unroll
            for (int jj = 0; jj < 4; jj++) up2(acc[i][jj], v8[2 * jj], v8[2 * jj + 1]);
            float* op = outp + ((size_t)b * TN + t) * 64 + f0;
            *reinterpret_cast<float4*>(op) = make_float4(v8[0], v8[1], v8[2], v8[3]);
            *reinterpret_cast<float4*>(op + 4) = make_float4(v8[4], v8[5], v8[6], v8[7]);
        }
    }
}

// ---------------- conv1 epilogue: t1 = relu(LN(p0+p1+bias)) + res ------------
__global__ void __launch_bounds__(256, 8)
k_conv1ln(const float* __restrict__ b1,
          const float* __restrict__ lns, const float* __restrict__ lnb) {
    int b = blockIdx.y;
    int t0 = blockIdx.x * 128;
    int tid = threadIdx.x;
    int tg = tid >> 3, fg = tid & 7;
    int f0 = fg * 8, u0 = tg * 4;

    float ls[8], lb[8], bi[8];
    #pragma unroll
    for (int j = 0; j < 8; j++) {
        ls[j] = lns[f0 + j];
        lb[j] = lnb[f0 + j];
        bi[j] = b1[f0 + j];
    }

    #pragma unroll
    for (int i = 0; i < 4; i++) {
        int t = t0 + u0 + i;
        if (t < TN) {
            size_t off = ((size_t)b * TN + t) * 64 + f0;
            float4 a0 = *reinterpret_cast<const float4*>(g_p0 + off);
            float4 a1 = *reinterpret_cast<const float4*>(g_p0 + off + 4);
            float4 b0 = *reinterpret_cast<const float4*>(g_p1 + off);
            float4 b1v = *reinterpret_cast<const float4*>(g_p1 + off + 4);
            float a8[8] = {a0.x + b0.x, a0.y + b0.y, a0.z + b0.z, a0.w + b0.w,
                           a1.x + b1v.x, a1.y + b1v.y, a1.z + b1v.z, a1.w + b1v.w};
            #pragma unroll
            for (int j = 0; j < 8; j++) a8[j] += bi[j];

            float s = 0.f, ss = 0.f;
            #pragma unroll
            for (int j = 0; j < 8; j++) { s += a8[j]; ss += a8[j] * a8[j]; }
            #pragma unroll
            for (int o = 1; o < 8; o <<= 1) {
                s  += __shfl_xor_sync(0xffffffffu, s, o);
                ss += __shfl_xor_sync(0xffffffffu, ss, o);
            }
            float m = s * (1.0f / 64.0f);
            float v = ss * (1.0f / 64.0f) - m * m;
            float rstd = rsqrtf(v + 1e-6f);

            float4 r0v = *reinterpret_cast<const float4*>(g_res + off);
            float4 r1v = *reinterpret_cast<const float4*>(g_res + off + 4);
            float r8[8] = {r0v.x, r0v.y, r0v.z, r0v.w, r1v.x, r1v.y, r1v.z, r1v.w};
            float o8[8];
            #pragma unroll
            for (int j = 0; j < 8; j++) {
                float h = fmaxf((a8[j] - m) * rstd * ls[j] + lb[j], 0.f);
                o8[j] = h + r8[j];
            }
            float* op = g_t1 + off;
            *reinterpret_cast<float4*>(op) = make_float4(o8[0], o8[1], o8[2], o8[3]);
            *reinterpret_cast<float4*>(op + 4) = make_float4(o8[4], o8[5], o8[6], o8[7]);
        } else {
            float s = 0.f, ss = 0.f;
            #pragma unroll
            for (int o = 1; o < 8; o <<= 1) {
                s  += __shfl_xor_sync(0xffffffffu, s, o);
                ss += __shfl_xor_sync(0xffffffffu, ss, o);
            }
        }
    }
}

// ---------------- conv (F->F, dilation D) + LN + relu + identity res ---------
template <int D>
__global__ void __launch_bounds__(256, 2)
k_convres(const float* __restrict__ in,
          const float* __restrict__ w, const float* __restrict__ bias,
          const float* __restrict__ lns, const float* __restrict__ lnb,
          float* __restrict__ outp) {
    extern __shared__ float sm[];
    const int ROWS = 128 + 2 * D;
    float* Ts = sm;                 // ROWS x 65
    float* Ws = sm + ROWS * 65;     // 3*64*64
    int b = blockIdx.y;
    int t0 = blockIdx.x * 128;
    int tid = threadIdx.x;
    const float* inb = in + (size_t)b * TN * 64;

    for (int idx = tid; idx < ROWS * 64; idx += 256) {
        int u = idx >> 6, f = idx & 63;
        int t = t0 - D + u;
        Ts[u * 65 + f] = (t >= 0 && t < TN) ? inb[(size_t)t * 64 + f] : 0.f;
    }
    for (int idx = tid; idx < 3 * 64 * 64; idx += 256) Ws[idx] = w[idx];
    __syncthreads();

    int tg = tid >> 3, fg = tid & 7;
    int f0 = fg * 8;
    int u0 = tg * 4;

    float ls[8], lb[8];
    ull acc[4][4];
    #pragma unroll
    for (int jj = 0; jj < 4; jj++) {
        ull bj = pk2(bias[f0 + 2 * jj], bias[f0 + 2 * jj + 1]);
        #pragma unroll
        for (int i = 0; i < 4; i++) acc[i][jj] = bj;
    }
    #pragma unroll
    for (int j = 0; j < 8; j++) { ls[j] = lns[f0 + j]; lb[j] = lnb[f0 + j]; }

    #pragma unroll 2
    for (int c = 0; c < 64; c++) {
        ull xd[2 * D + 4];
        #pragma unroll
        for (int s = 0; s < 2 * D + 4; s++) xd[s] = d2(Ts[(u0 + s) * 65 + c]);
        #pragma unroll
        for (int tap = 0; tap < 3; tap++) {
            const ull* wp = reinterpret_cast<const ull*>(&Ws[tap * 4096 + c * 64 + f0]);
            #pragma unroll
            for (int jj = 0; jj < 4; jj++) {
                ull wv = wp[jj];
                #pragma unroll
                for (int i = 0; i < 4; i++) fma2(acc[i][jj], xd[i + tap * D], wv);
            }
        }
    }

    #pragma unroll
    for (int i = 0; i < 4; i++) {
        float a8[8];
        #pragma unroll
        for (int jj = 0; jj < 4; jj++) up2(acc[i][jj], a8[2 * jj], a8[2 * jj + 1]);
        float s = 0.f, ss = 0.f;
        #pragma unroll
        for (int j = 0; j < 8; j++) { s += a8[j]; ss += a8[j] * a8[j]; }
        #pragma unroll
        for (int o = 1; o < 8; o <<= 1) {
            s  += __shfl_xor_sync(0xffffffffu, s, o);
            ss += __shfl_xor_sync(0xffffffffu, ss, o);
        }
        float m = s * (1.0f / 64.0f);
        float v = ss * (1.0f / 64.0f) - m * m;
        float rstd = rsqrtf(v + 1e-6f);
        int t = t0 + u0 + i;
        if (t < TN) {
            float o8[8];
            #pragma unroll
            for (int j = 0; j < 8; j++) {
                float h = fmaxf((a8[j] - m) * rstd * ls[j] + lb[j], 0.f);
                o8[j] = h + Ts[(u0 + i + D) * 65 + f0 + j];
            }
            float* op = outp + ((size_t)b * TN + t) * 64 + f0;
            *reinterpret_cast<float4*>(op) = make_float4(o8[0], o8[1], o8[2], o8[3]);
            *reinterpret_cast<float4*>(op + 4) = make_float4(o8[4], o8[5], o8[6], o8[7]);
        }
    }
}

// ---------------- node_feats = X @ tcn_out, K split over 2 CTAs --------------
__global__ void k_nf(const float* __restrict__ X) {
    __shared__ float Xs[128][33];
    __shared__ float Ts[32][64];
    int half = blockIdx.x;
    int b = blockIdx.y;
    int tid = threadIdx.x;
    int c0 = (tid >> 4) * 8;
    int f0 = (tid & 15) * 4;
    ull acc[8][2];
    #pragma unroll
    for (int r = 0; r < 8; r++) { acc[r][0] = 0ull; acc[r][1] = 0ull; }

    const float* Xb = X + (size_t)b * CC * TN;
    const float* Tb = g_tcn + (size_t)b * TN * 64;
    int kbeg = half * 1000, kend = kbeg + 1000;

    for (int k0 = kbeg; k0 < kend; k0 += 32) {
        for (int idx = tid; idx < 128 * 32; idx += 256) {
            int c = idx >> 5, kk = idx & 31;
            int k = k0 + kk;
            Xs[c][kk] = (k < kend) ? Xb[(size_t)c * TN + k] : 0.f;
        }
        for (int idx = tid; idx < 32 * 64; idx += 256) {
            int kk = idx >> 6, f = idx & 63;
            int k = k0 + kk;
            Ts[kk][f] = (k < kend) ? Tb[(size_t)k * 64 + f] : 0.f;
        }
        __syncthreads();
        #pragma unroll 4
        for (int kk = 0; kk < 32; kk++) {
            const ull* tp = reinterpret_cast<const ull*>(&Ts[kk][f0]);
            ull t0v = tp[0], t1v = tp[1];
            #pragma unroll
            for (int r = 0; r < 8; r++) {
                ull xd = d2(Xs[c0 + r][kk]);
                fma2(acc[r][0], xd, t0v);
                fma2(acc[r][1], xd, t1v);
            }
        }
        __syncthreads();
    }
    #pragma unroll
    for (int r = 0; r < 8; r++) {
        float v4[4];
        up2(acc[r][0], v4[0], v4[1]);
        up2(acc[r][1], v4[2], v4[3]);
        float* o = g_nf + (size_t)half * BB * CC * FF + ((size_t)b * 128 + c0 + r) * 64 + f0;
        *reinterpret_cast<float4*>(o) = make_float4(v4[0], v4[1], v4[2], v4[3]);
    }
}

// ---------------- geo = relu(LN(adj @ node_feats)) ---------------------------
__global__ void k_geo(const float* __restrict__ lns, const float* __restrict__ lnb) {
    extern __shared__ float sm[];
    float* adjs = sm;                // 128 x 129 (pad)
    float* nfs = sm + 128 * 129;     // 128 x 64
    int b = blockIdx.x, tid = threadIdx.x;   // 128 threads
    for (int idx = tid; idx < 128 * 64; idx += 128)
        nfs[idx] = g_nf[(size_t)b * 8192 + idx] + g_nf[(size_t)BB * 8192 + (size_t)b * 8192 + idx];
    {
        const float* src = g_adj + (size_t)b * 16384;
        for (int idx = tid; idx < 16384; idx += 128) {
            int i = idx >> 7, j = idx & 127;
            adjs[i * 129 + j] = src[idx];
        }
    }
    __syncthreads();

    const float* arow = adjs + tid * 129;
    ull acc[32];
    #pragma unroll
    for (int q = 0; q < 32; q++) acc[q] = 0ull;
    #pragma unroll 2
    for (int j = 0; j < 128; j++) {
        ull a = d2(arow[j]);
        const ull* n2 = reinterpret_cast<const ull*>(&nfs[j * 64]);
        #pragma unroll
        for (int q = 0; q < 32; q++) fma2(acc[q], a, n2[q]);
    }
    float av[64];
    #pragma unroll
    for (int q = 0; q < 32; q++) up2(acc[q], av[2 * q], av[2 * q + 1]);
    float s = 0.f, ss = 0.f;
    #pragma unroll
    for (int j = 0; j < 64; j++) { s += av[j]; ss += av[j] * av[j]; }
    float m = s * (1.0f / 64.0f);
    float v = ss * (1.0f / 64.0f) - m * m;
    float rstd = rsqrtf(v + 1e-6f);
    float* o = g_geo + ((size_t)b * 128 + tid) * 64;
    #pragma unroll
    for (int j = 0; j < 64; j++)
        o[j] = fmaxf((av[j] - m) * rstd * lns[j] + lnb[j], 0.f);
}

// ---------------- decay GEMV partials: 4 K-chunks per batch row --------------
__global__ void k_decay(const float* __restrict__ dw) {
    __shared__ float gs[2048];
    int part = blockIdx.x, b = blockIdx.y;
    int tid = threadIdx.x;  // 128 threads
    int kbeg = part * 2048;
    for (int idx = tid; idx < 2048; idx += 128)
        gs[idx] = g_geo[(size_t)b * 8192 + kbeg + idx];
    __syncthreads();
    float a0 = 0.f, a1 = 0.f, a2 = 0.f, a3 = 0.f;
    for (int k = 0; k < 2048; k += 4) {
        a0 += gs[k + 0] * dw[(size_t)(kbeg + k + 0) * 128 + tid];
        a1 += gs[k + 1] * dw[(size_t)(kbeg + k + 1) * 128 + tid];
        a2 += gs[k + 2] * dw[(size_t)(kbeg + k + 2) * 128 + tid];
        a3 += gs[k + 3] * dw[(size_t)(kbeg + k + 3) * 128 + tid];
    }
    g_dpart[((size_t)part * BB + b) * HH + tid] = (a0 + a1) + (a2 + a3);
}

// ---------------- chunk-mean pool of tcn + seq_w GEMM ------------------------
__global__ void k_poolseq(const float* __restrict__ sw, const float* __restrict__ sb) {
    __shared__ float ps[64];
    int s = blockIdx.x, b = blockIdx.y, tid = threadIdx.x;  // 128 threads
    if (tid < 64) {
        const float* base = g_tcn + ((size_t)b * TN + s * 200) * 64 + tid;
        float a = 0.f;
        #pragma unroll 8
        for (int t = 0; t < 200; t++) a += base[(size_t)t * 64];
        ps[tid] = a * (1.0f / 200.0f);
    }
    __syncthreads();
    float acc = sb[tid];
    #pragma unroll
    for (int f = 0; f < 64; f++) acc += ps[f] * sw[f * 128 + tid];
    g_seqin[((size_t)b * SEQN + s) * 128 + tid] = acc;
}

// ---------------- LIF scan + attention + heads -------------------------------
__global__ void k_lif(const float* __restrict__ db,
                      const float* __restrict__ aw, const float* __restrict__ ab,
                      const float* __restrict__ fw, const float* __restrict__ fb,
                      const float* __restrict__ ow, const float* __restrict__ ob,
                      float* __restrict__ dout) {
    __shared__ float red[128];
    __shared__ float attn[SEQN];
    __shared__ float featv[128];
    __shared__ float f2[64];
    int b = blockIdx.x, h = threadIdx.x;   // 128 threads

    float dacc = db[h]
        + g_dpart[((size_t)0 * BB + b) * HH + h]
        + g_dpart[((size_t)1 * BB + b) * HH + h]
        + g_dpart[((size_t)2 * BB + b) * HH + h]
        + g_dpart[((size_t)3 * BB + b) * HH + h];
    float d = 1.0f / (1.0f + expf(-dacc));

    float mem = 0.f, spsum = 0.f;
    float sp[SEQN];
    #pragma unroll
    for (int s = 0; s < SEQN; s++) {
        mem = mem * d + g_seqin[((size_t)b * SEQN + s) * 128 + h];
        float spike = (mem - 0.5f) > 0.f ? 1.0f : 0.0f;
        sp[s] = spike;
        spsum += spike;
        mem -= 0.5f * spike;
    }
    float awh = aw[h];
    for (int s = 0; s < SEQN; s++) {
        red[h] = sp[s] * awh;
        __syncthreads();
        for (int o = 64; o; o >>= 1) {
            if (h < o) red[h] += red[h + o];
            __syncthreads();
        }
        if (h == 0) attn[s] = red[0] + ab[0];
        __syncthreads();
    }
    red[h] = spsum;
    __syncthreads();
    for (int o = 64; o; o >>= 1) {
        if (h < o) red[h] += red[h + o];
        __syncthreads();
    }
    if (h == 0) atomicAdd(&g_spksum, red[0]);

    if (h == 0) {
        float mx = -1e30f;
        for (int s = 0; s < SEQN; s++) mx = fmaxf(mx, attn[s]);
        float ssum = 0.f;
        for (int s = 0; s < SEQN; s++) { attn[s] = expf(attn[s] - mx); ssum += attn[s]; }
        float inv = 1.0f / ssum;
        for (int s = 0; s < SEQN; s++) attn[s] *= inv;
    }
    __syncthreads();

    float fv = 0.f;
    #pragma unroll
    for (int s = 0; s < SEQN; s++) fv += sp[s] * attn[s];
    featv[h] = fv;
    __syncthreads();

    if (h < 64) {
        float acc = fb[h];
        for (int k = 0; k < 128; k++) acc += featv[k] * fw[k * 64 + h];
        f2[h] = fmaxf(acc, 0.f);
    }
    __syncthreads();
    if (h < 4) {
        float acc = ob[h];
        for (int j = 0; j < 64; j++) acc += f2[j] * ow[j * 4 + h];
        dout[b * 4 + h] = acc;
    }
}

__global__ void k_finmean(float* __restrict__ dout, int osz) {
    if (threadIdx.x == 0)
        dout[osz - 1] = g_spksum * (1.0f / ((float)BB * SEQN * HH));
}

// ---------------- launcher ----------------------------------------------------
extern "C" void kernel_launch(void* const* d_in, const int* in_sizes, int n_in,
                              void* d_out, int out_size) {
    const float* X    = (const float*)d_in[0];
    const float* c1w  = (const float*)d_in[1];
    const float* c1b  = (const float*)d_in[2];
    const float* l1s  = (const float*)d_in[3];
    const float* l1b  = (const float*)d_in[4];
    const float* r1w  = (const float*)d_in[5];
    const float* r1b  = (const float*)d_in[6];
    const float* c2w  = (const float*)d_in[7];
    const float* c2b  = (const float*)d_in[8];
    const float* l2s  = (const float*)d_in[9];
    const float* l2b  = (const float*)d_in[10];
    const float* c3w  = (const float*)d_in[11];
    const float* c3b  = (const float*)d_in[12];
    const float* l3s  = (const float*)d_in[13];
    const float* l3b  = (const float*)d_in[14];
    const float* lgs  = (const float*)d_in[15];
    const float* lgb  = (const float*)d_in[16];
    const float* seqw = (const float*)d_in[19];
    const float* seqb = (const float*)d_in[20];
    const float* dw   = (const float*)d_in[21];
    const float* db   = (const float*)d_in[22];
    const float* aw   = (const float*)d_in[23];
    const float* ab   = (const float*)d_in[24];
    const float* fw   = (const float*)d_in[25];
    const float* fb   = (const float*)d_in[26];
    const float* ow   = (const float*)d_in[27];
    const float* ob   = (const float*)d_in[28];
    float* out = (float*)d_out;

    float *t1p, *t2p, *tcnp, *p0p, *p1p;
    cudaGetSymbolAddress((void**)&t1p, g_t1);
    cudaGetSymbolAddress((void**)&t2p, g_t2);
    cudaGetSymbolAddress((void**)&tcnp, g_tcn);
    cudaGetSymbolAddress((void**)&p0p, g_p0);
    cudaGetSymbolAddress((void**)&p1p, g_p1);

    size_t sm_log = (size_t)2 * 128 * 128 * sizeof(float);                 // 128 KB
    size_t sm_c1g = (size_t)(64 * 130 + 3 * 64 * 64) * sizeof(float);      // ~82 KB
    size_t sm_res = (size_t)(128 * 132) * sizeof(float);                   // 66 KB
    size_t sm_c2  = (size_t)(132 * 65 + 3 * 64 * 64) * sizeof(float);
    size_t sm_c3  = (size_t)(136 * 65 + 3 * 64 * 64) * sizeof(float);
    size_t sm_geo = (size_t)(128 * 129 + 128 * 64) * sizeof(float);
    cudaFuncSetAttribute(k_logadj, cudaFuncAttributeMaxDynamicSharedMemorySize, (int)sm_log);
    cudaFuncSetAttribute(k_conv1g, cudaFuncAttributeMaxDynamicSharedMemorySize, (int)sm_c1g);
    cudaFuncSetAttribute(k_res, cudaFuncAttributeMaxDynamicSharedMemorySize, (int)sm_res);
    cudaFuncSetAttribute(k_convres<2>, cudaFuncAttributeMaxDynamicSharedMemorySize, (int)sm_c2);
    cudaFuncSetAttribute(k_convres<4>, cudaFuncAttributeMaxDynamicSharedMemorySize, (int)sm_c3);
    cudaFuncSetAttribute(k_geo, cudaFuncAttributeMaxDynamicSharedMemorySize, (int)sm_geo);

    cudaStream_t s2 = 0;
    cudaEvent_t e1 = 0, e2 = 0, e3 = 0, e4 = 0, er = 0;
    bool fork = true;
    if (cudaStreamCreateWithFlags(&s2, cudaStreamNonBlocking) != cudaSuccess) fork = false;
    if (fork && cudaEventCreateWithFlags(&e1, cudaEventDisableTiming) != cudaSuccess) fork = false;
    if (fork && cudaEventCreateWithFlags(&e2, cudaEventDisableTiming) != cudaSuccess) fork = false;
    if (fork && cudaEventCreateWithFlags(&e3, cudaEventDisableTiming) != cudaSuccess) fork = false;
    if (fork && cudaEventCreateWithFlags(&e4, cudaEventDisableTiming) != cudaSuccess) fork = false;
    if (fork && cudaEventCreateWithFlags(&er, cudaEventDisableTiming) != cudaSuccess) fork = false;

    // anchor kernel on the origin stream (also zeroes g_spksum), then fork s2
    k_zero<<<1, 32>>>();

    if (fork) {
        cudaEventRecord(e1, 0);
        cudaStreamWaitEvent(s2, e1, 0);      // REQUIRED: joins s2 into the capture
        {   // side chain: res (needed by conv1ln) then cov -> logadj
            dim3 gr(16, BB);
            k_res<<<gr, 256, sm_res, s2>>>(X, r1w, r1b);
        }
        cudaEventRecord(er, s2);
        k_cov<<<BB, 256, 0, s2>>>(X);
        k_logadj<<<BB, 256, sm_log, s2>>>();
        cudaEventRecord(e2, s2);
    } else {
        dim3 gr(16, BB);
        k_res<<<gr, 256, sm_res>>>(X, r1w, r1b);
        k_cov<<<BB, 256>>>(X);
        k_logadj<<<BB, 256, sm_log>>>();
    }

    {
        dim3 g1(16, BB, 2);
        k_conv1g<<<g1, 256, sm_c1g>>>(X, c1w, p0p, p1p);
    }
    if (fork) cudaStreamWaitEvent(0, er, 0);    // res before conv1ln
    {
        dim3 gl(16, BB);
        k_conv1ln<<<gl, 256>>>(c1b, l1s, l1b);
        dim3 g(16, BB);
        k_convres<2><<<g, 256, sm_c2>>>(t1p, c2w, c2b, l2s, l2b, t2p);
        k_convres<4><<<g, 256, sm_c3>>>(t2p, c3w, c3b, l3s, l3b, tcnp);
    }

    if (fork) {
        cudaEventRecord(e3, 0);          // tcn ready
        cudaStreamWaitEvent(s2, e3, 0);
        dim3 gp(SEQN, BB);
        k_poolseq<<<gp, 128, 0, s2>>>(seqw, seqb);
        cudaEventRecord(e4, s2);
    }

    {
        dim3 g(2, BB);
        k_nf<<<g, 256>>>(X);
    }
    if (!fork) {
        dim3 gp(SEQN, BB);
        k_poolseq<<<gp, 128>>>(seqw, seqb);
    }

    if (fork) cudaStreamWaitEvent(0, e2, 0);   // adj ready

    k_geo<<<BB, 128, sm_geo>>>(lgs, lgb);
    {
        dim3 g(4, BB);
        k_decay<<<g, 128>>>(dw);
    }

    if (fork) cudaStreamWaitEvent(0, e4, 0);   // seqin ready

    k_lif<<<BB, 128>>>(db, aw, ab, fw, fb, ow, ob, out);
    k_finmean<<<1, 32>>>(out, out_size);
}

// round 14
// speedup vs baseline: 1.0683x; 1.0683x over previous
#include <cuda_runtime.h>
#include <math.h>

#define BB 128
#define CC 128
#define TN 2000
#define FF 64
#define HH 128
#define SEQN 10

typedef unsigned long long ull;

// ---- packed f32x2 helpers (sm_103a) -----------------------------------------
__device__ __forceinline__ ull d2(float x) {
    ull r; asm("mov.b64 %0, {%1, %1};" : "=l"(r) : "f"(x)); return r;
}
__device__ __forceinline__ ull pk2(float a, float b) {
    ull r; asm("mov.b64 %0, {%1, %2};" : "=l"(r) : "f"(a), "f"(b)); return r;
}
__device__ __forceinline__ void up2(ull v, float& a, float& b) {
    asm("mov.b64 {%0, %1}, %2;" : "=f"(a), "=f"(b) : "l"(v));
}
__device__ __forceinline__ void fma2(ull& d, ull a, ull b) {
    asm("fma.rn.f32x2 %0, %1, %2, %0;" : "+l"(d) : "l"(a), "l"(b));
}
__device__ __forceinline__ ull mul2(ull a, ull b) {
    ull r; asm("mul.rn.f32x2 %0, %1, %2;" : "=l"(r) : "l"(a), "l"(b)); return r;
}

// ---------------- scratch (device globals; no runtime allocation) -------------
__device__ float g_Ms[BB*CC*CC];     // M = I - cov/c (symmetric)
__device__ float g_cpar[BB*2];       // {invc, logc} per batch
__device__ float g_adj[BB*CC*CC];
__device__ float g_res[BB*TN*FF];
__device__ float g_t1[BB*TN*FF];     // relu(LN(conv1)); res added at cr2 load
__device__ float g_t2[BB*TN*FF];
__device__ float g_tcn[BB*TN*FF];
__device__ float g_nf[2*BB*CC*FF];
__device__ float g_geo[BB*CC*FF];
__device__ float g_dpart[4*BB*HH];
__device__ float g_seqin[BB*SEQN*HH];
__device__ float g_spksum;

// ---------------- tiny anchor kernel (spksum zero + fork anchor) --------------
__global__ void k_zero() {
    if (threadIdx.x == 0) g_spksum = 0.0f;
}

// ---------------- cov + mean + trace + M: one CTA per batch ------------------
__global__ void __launch_bounds__(256, 1) k_cov(const float* __restrict__ X) {
    __shared__ float Xs[32 * 130];
    __shared__ float mn[128];
    __shared__ float red[256];
    __shared__ float csh[2];
    int b = blockIdx.x, tid = threadIdx.x;
    const float* Xb = X + (size_t)b * CC * TN;

    int ty = tid >> 4, tx = tid & 15;
    int r0 = ty * 8, c0 = tx * 8;
    int kkl = tid & 31, iw = tid >> 5;   // lane, warp

    float rsum[16];
    #pragma unroll
    for (int j = 0; j < 16; j++) rsum[j] = 0.f;

    ull acc[8][4];
    #pragma unroll
    for (int i = 0; i < 8; i++)
        #pragma unroll
        for (int jj = 0; jj < 4; jj++) acc[i][jj] = 0ull;

    for (int k0 = 0; k0 < TN; k0 += 32) {
        int k = k0 + kkl;
        bool ok = (k < TN);
        #pragma unroll 4
        for (int j = 0; j < 16; j++) {
            int i = iw + 8 * j;
            float v = ok ? Xb[(size_t)i * TN + k] : 0.f;
            Xs[kkl * 130 + i] = v;
            rsum[j] += v;
        }
        __syncthreads();
        #pragma unroll 4
        for (int kk = 0; kk < 32; kk++) {
            const float* row = &Xs[kk * 130];
            const ull* ap = reinterpret_cast<const ull*>(row + r0);
            const ull* bp = reinterpret_cast<const ull*>(row + c0);
            ull b0 = bp[0], b1 = bp[1], b2 = bp[2], b3 = bp[3];
            float a8[8];
            up2(ap[0], a8[0], a8[1]); up2(ap[1], a8[2], a8[3]);
            up2(ap[2], a8[4], a8[5]); up2(ap[3], a8[6], a8[7]);
            #pragma unroll
            for (int i = 0; i < 8; i++) {
                ull ad = d2(a8[i]);
                fma2(acc[i][0], ad, b0);
                fma2(acc[i][1], ad, b1);
                fma2(acc[i][2], ad, b2);
                fma2(acc[i][3], ad, b3);
            }
        }
        __syncthreads();
    }

    #pragma unroll
    for (int j = 0; j < 16; j++) {
        float s = rsum[j];
        #pragma unroll
        for (int o = 16; o; o >>= 1) s += __shfl_xor_sync(0xffffffffu, s, o);
        if (kkl == 0) mn[iw + 8 * j] = s * (1.0f / TN);
    }
    __syncthreads();

    float dsum = 0.f;
    if (ty == tx) {
        #pragma unroll
        for (int i = 0; i < 8; i++) {
            float lo, hi;
            up2(acc[i][i >> 1], lo, hi);
            float raw = (i & 1) ? hi : lo;
            float mi = mn[r0 + i];
            dsum += (raw - (float)TN * mi * mi) * (1.0f / (TN - 1)) + 1e-4f;
        }
    }
    red[tid] = dsum;
    __syncthreads();
    for (int o = 128; o; o >>= 1) {
        if (tid < o) red[tid] += red[tid + o];
        __syncthreads();
    }
    if (tid == 0) {
        float c = 1.06f * red[0] * (1.0f / 128.0f);
        csh[0] = 1.0f / c;
        csh[1] = logf(c);
        g_cpar[b * 2 + 0] = csh[0];
        g_cpar[b * 2 + 1] = csh[1];
    }
    __syncthreads();
    float invc = csh[0];

    float* Mb = g_Ms + (size_t)b * CC * CC;
    #pragma unroll
    for (int i = 0; i < 8; i++) {
        int gi = r0 + i;
        float mi = mn[gi];
        float v8[8];
        #pragma unroll
        for (int jj = 0; jj < 4; jj++) up2(acc[i][jj], v8[2 * jj], v8[2 * jj + 1]);
        #pragma unroll
        for (int j = 0; j < 8; j++) {
            int gj = c0 + j;
            float v = (v8[j] - (float)TN * mi * mn[gj]) * (1.0f / (TN - 1));
            if (gi == gj) v += 1e-4f;
            v8[j] = ((gi == gj) ? 1.0f : 0.0f) - v * invc;
        }
        float* op = Mb + (size_t)gi * CC + c0;
        *reinterpret_cast<float4*>(op) = make_float4(v8[0], v8[1], v8[2], v8[3]);
        *reinterpret_cast<float4*>(op + 4) = make_float4(v8[4], v8[5], v8[6], v8[7]);
    }
}

// ---------------- matrix log via Paterson-Stockmeyer (5 matmuls) -------------
__global__ void __launch_bounds__(256, 1) k_logadj() {
    extern __shared__ float sm[];
    float* Ps = sm;            // holds M initially, then P
    float* Ws = sm + 16384;    // W = M^2
    int b = blockIdx.x, tid = threadIdx.x;
    const float* Mb = g_Ms + (size_t)b * CC * CC;
    float logc = g_cpar[b * 2 + 1];

    for (int idx = tid; idx < 4096; idx += 256)
        reinterpret_cast<float4*>(Ps)[idx] = __ldg(reinterpret_cast<const float4*>(Mb) + idx);
    __syncthreads();

    int ty = tid >> 4, tx = tid & 15;
    int r0 = ty * 8, c0 = tx * 8;

    ull Mt2[8][4];
    #pragma unroll
    for (int i = 0; i < 8; i++) {
        const ull* mp = reinterpret_cast<const ull*>(&Ps[(r0 + i) * 128 + c0]);
        #pragma unroll
        for (int jj = 0; jj < 4; jj++) Mt2[i][jj] = mp[jj];
    }

    // ---- W = M^2 ----
    {
        ull acc[8][4];
        #pragma unroll
        for (int i = 0; i < 8; i++)
            #pragma unroll
            for (int jj = 0; jj < 4; jj++) acc[i][jj] = 0ull;
        #pragma unroll 2
        for (int kk = 0; kk < 128; kk++) {
            float4 p0 = *reinterpret_cast<const float4*>(&Ps[kk * 128 + r0]);
            float4 p1 = *reinterpret_cast<const float4*>(&Ps[kk * 128 + r0 + 4]);
            const ull* mp = reinterpret_cast<const ull*>(&Ps[kk * 128 + c0]);
            ull m0 = mp[0], m1 = mp[1], m2 = mp[2], m3 = mp[3];
            ull pd[8] = {d2(p0.x), d2(p0.y), d2(p0.z), d2(p0.w),
                         d2(p1.x), d2(p1.y), d2(p1.z), d2(p1.w)};
            #pragma unroll
            for (int i = 0; i < 8; i++) {
                fma2(acc[i][0], pd[i], m0);
                fma2(acc[i][1], pd[i], m1);
                fma2(acc[i][2], pd[i], m2);
                fma2(acc[i][3], pd[i], m3);
            }
        }
        #pragma unroll
        for (int i = 0; i < 8; i++) {
            ull* wp = reinterpret_cast<ull*>(&Ws[(r0 + i) * 128 + c0]);
            #pragma unroll
            for (int jj = 0; jj < 4; jj++) wp[jj] = acc[i][jj];
        }
        __syncthreads();
    }

    // ---- init P = W/10 + I/8 + M/9 ----
    {
        ull c10 = d2(0.1f), c9 = d2(1.0f / 9.0f);
        #pragma unroll
        for (int i = 0; i < 8; i++) {
            const ull* wp = reinterpret_cast<const ull*>(&Ws[(r0 + i) * 128 + c0]);
            ull* pp = reinterpret_cast<ull*>(&Ps[(r0 + i) * 128 + c0]);
            #pragma unroll
            for (int jj = 0; jj < 4; jj++) {
                ull v = mul2(wp[jj], c10);
                fma2(v, Mt2[i][jj], c9);
                float lo, hi;
                up2(v, lo, hi);
                int gi = r0 + i;
                if (gi == c0 + 2 * jj)     lo += 0.125f;
                if (gi == c0 + 2 * jj + 1) hi += 0.125f;
                pp[jj] = pk2(lo, hi);
            }
        }
        __syncthreads();
    }

    const float aj[4] = {1.0f / 6.0f, 0.25f, 0.5f, 0.0f};
    const float bj[4] = {1.0f / 7.0f, 0.2f, 1.0f / 3.0f, 1.0f};

    ull acc[8][4];
    for (int step = 0; step < 4; step++) {
        #pragma unroll
        for (int i = 0; i < 8; i++)
            #pragma unroll
            for (int jj = 0; jj < 4; jj++) acc[i][jj] = 0ull;

        #pragma unroll 2
        for (int kk = 0; kk < 128; kk++) {
            float4 p0 = *reinterpret_cast<const float4*>(&Ps[kk * 128 + r0]);
            float4 p1 = *reinterpret_cast<const float4*>(&Ps[kk * 128 + r0 + 4]);
            const ull* wp = reinterpret_cast<const ull*>(&Ws[kk * 128 + c0]);
            ull w0 = wp[0], w1 = wp[1], w2 = wp[2], w3 = wp[3];
            ull pd[8] = {d2(p0.x), d2(p0.y), d2(p0.z), d2(p0.w),
                         d2(p1.x), d2(p1.y), d2(p1.z), d2(p1.w)};
            #pragma unroll
            for (int i = 0; i < 8; i++) {
                fma2(acc[i][0], pd[i], w0);
                fma2(acc[i][1], pd[i], w1);
                fma2(acc[i][2], pd[i], w2);
                fma2(acc[i][3], pd[i], w3);
            }
        }

        ull bjd = d2(bj[step]);
        #pragma unroll
        for (int i = 0; i < 8; i++)
            #pragma unroll
            for (int jj = 0; jj < 4; jj++) fma2(acc[i][jj], Mt2[i][jj], bjd);

        if (step < 3) {
            float av = aj[step];
            __syncthreads();
            #pragma unroll
            for (int i = 0; i < 8; i++) {
                ull* pp = reinterpret_cast<ull*>(&Ps[(r0 + i) * 128 + c0]);
                int gi = r0 + i;
                #pragma unroll
                for (int jj = 0; jj < 4; jj++) {
                    ull v = acc[i][jj];
                    if (gi == c0 + 2 * jj || gi == c0 + 2 * jj + 1) {
                        float lo, hi;
                        up2(v, lo, hi);
                        if (gi == c0 + 2 * jj)     lo += av;
                        else                        hi += av;
                        v = pk2(lo, hi);
                    }
                    pp[jj] = v;
                }
            }
            __syncthreads();
        }
    }

    #pragma unroll
    for (int i = 0; i < 8; i++) {
        float La[8];
        #pragma unroll
        for (int jj = 0; jj < 4; jj++) {
            float lo, hi;
            up2(acc[i][jj], lo, hi);
            La[2 * jj] = -lo;
            La[2 * jj + 1] = -hi;
        }
        int dj = (r0 + i) - c0;
        if (dj >= 0 && dj < 8) La[dj] += logc;

        float mx = -1e30f;
        #pragma unroll
        for (int j = 0; j < 8; j++) mx = fmaxf(mx, La[j]);
        #pragma unroll
        for (int o = 1; o < 16; o <<= 1) mx = fmaxf(mx, __shfl_xor_sync(0xffffffffu, mx, o));
        float e[8], s = 0.f;
        #pragma unroll
        for (int j = 0; j < 8; j++) { e[j] = expf(La[j] - mx); s += e[j]; }
        #pragma unroll
        for (int o = 1; o < 16; o <<= 1) s += __shfl_xor_sync(0xffffffffu, s, o);
        float inv = 1.0f / s;
        float* outp = g_adj + ((size_t)b * 128 + r0 + i) * 128 + c0;
        *reinterpret_cast<float4*>(outp) =
            make_float4(e[0] * inv, e[1] * inv, e[2] * inv, e[3] * inv);
        *reinterpret_cast<float4*>(outp + 4) =
            make_float4(e[4] * inv, e[5] * inv, e[6] * inv, e[7] * inv);
    }
}

// ---------------- res GEMM: g_res = X_t @ rw + rb ----------------------------
__global__ void __launch_bounds__(256, 3)
k_res(const float* __restrict__ X, const float* __restrict__ rw,
      const float* __restrict__ rb) {
    extern __shared__ float sm[];
    float* Xs = sm;               // 128 c x 132
    int b = blockIdx.y;
    int t0 = blockIdx.x * 128;
    int tid = threadIdx.x;
    int warp = tid >> 5, lane = tid & 31;
    const float* Xb = X + (size_t)b * CC * TN;

    for (int c = warp; c < 128; c += 8) {
        const float* src = Xb + (size_t)c * TN + t0;
        int u = lane * 4;
        float4 v;
        if (t0 + u + 3 < TN) {
            v = *reinterpret_cast<const float4*>(src + u);
        } else {
            v.x = (t0 + u     < TN) ? src[u]     : 0.f;
            v.y = (t0 + u + 1 < TN) ? src[u + 1] : 0.f;
            v.z = (t0 + u + 2 < TN) ? src[u + 2] : 0.f;
            v.w = 0.f;
        }
        *reinterpret_cast<float4*>(&Xs[c * 132 + u]) = v;
    }
    __syncthreads();

    int tg = tid >> 3, fg = tid & 7;
    int f0 = fg * 8, u0 = tg * 4;

    ull acc[4][4];
    #pragma unroll
    for (int jj = 0; jj < 4; jj++) {
        ull bj = pk2(rb[f0 + 2 * jj], rb[f0 + 2 * jj + 1]);
        #pragma unroll
        for (int i = 0; i < 4; i++) acc[i][jj] = bj;
    }

    #pragma unroll 4
    for (int c = 0; c < 128; c++) {
        ull xd[4];
        #pragma unroll
        for (int s = 0; s < 4; s++) xd[s] = d2(Xs[c * 132 + u0 + s]);
        const ull* rp = reinterpret_cast<const ull*>(rw + c * 64 + f0);
        #pragma unroll
        for (int jj = 0; jj < 4; jj++) {
            ull wv = __ldg(rp + jj);
            #pragma unroll
            for (int i = 0; i < 4; i++) fma2(acc[i][jj], xd[i], wv);
        }
    }

    #pragma unroll
    for (int i = 0; i < 4; i++) {
        int t = t0 + u0 + i;
        if (t < TN) {
            float v8[8];
            #pragma unroll
            for (int jj = 0; jj < 4; jj++) up2(acc[i][jj], v8[2 * jj], v8[2 * jj + 1]);
            float* op = g_res + ((size_t)b * TN + t) * 64 + f0;
            *reinterpret_cast<float4*>(op) = make_float4(v8[0], v8[1], v8[2], v8[3]);
            *reinterpret_cast<float4*>(op + 4) = make_float4(v8[4], v8[5], v8[6], v8[7]);
        }
    }
}

// ---------------- conv1 (C=128 -> F=64) + LN + relu (monolithic) -------------
__global__ void __launch_bounds__(512, 1)
k_conv1(const float* __restrict__ X,
        const float* __restrict__ w1, const float* __restrict__ b1,
        const float* __restrict__ lns, const float* __restrict__ lnb) {
    extern __shared__ float sm[];
    float* Xs = sm;                 // 128 x 258
    float* Ws = sm + 128 * 258;     // 3*128*64
    int b = blockIdx.y;
    int t0 = blockIdx.x * 256;
    int tid = threadIdx.x;
    int warp = tid >> 5, lane = tid & 31;
    const float* Xb = X + (size_t)b * CC * TN;

    for (int c = warp; c < 128; c += 16) {
        const float* src = Xb + (size_t)c * TN;
        for (int u = lane; u < 258; u += 32) {
            int t = t0 - 1 + u;
            Xs[c * 258 + u] = (t >= 0 && t < TN) ? src[t] : 0.f;
        }
    }
    for (int idx = tid; idx < 3 * 128 * 64; idx += 512) Ws[idx] = w1[idx];
    __syncthreads();

    int tg = tid >> 3, fg = tid & 7;
    int f0 = fg * 8, u0 = tg * 4;

    float ls[8], lb[8];
    ull acc[4][4];
    #pragma unroll
    for (int jj = 0; jj < 4; jj++) {
        ull bj = pk2(b1[f0 + 2 * jj], b1[f0 + 2 * jj + 1]);
        #pragma unroll
        for (int i = 0; i < 4; i++) acc[i][jj] = bj;
    }
    #pragma unroll
    for (int j = 0; j < 8; j++) { ls[j] = lns[f0 + j]; lb[j] = lnb[f0 + j]; }

    #pragma unroll 2
    for (int c = 0; c < 128; c++) {
        ull xd[6];
        #pragma unroll
        for (int s = 0; s < 6; s++) xd[s] = d2(Xs[c * 258 + u0 + s]);
        #pragma unroll
        for (int tap = 0; tap < 3; tap++) {
            const ull* wp = reinterpret_cast<const ull*>(&Ws[tap * 8192 + c * 64 + f0]);
            #pragma unroll
            for (int jj = 0; jj < 4; jj++) {
                ull wv = wp[jj];
                #pragma unroll
                for (int i = 0; i < 4; i++) fma2(acc[i][jj], xd[i + tap], wv);
            }
        }
    }

    #pragma unroll
    for (int i = 0; i < 4; i++) {
        float a8[8];
        #pragma unroll
        for (int jj = 0; jj < 4; jj++) up2(acc[i][jj], a8[2 * jj], a8[2 * jj + 1]);
        float s = 0.f, ss = 0.f;
        #pragma unroll
        for (int j = 0; j < 8; j++) { s += a8[j]; ss += a8[j] * a8[j]; }
        #pragma unroll
        for (int o = 1; o < 8; o <<= 1) {
            s  += __shfl_xor_sync(0xffffffffu, s, o);
            ss += __shfl_xor_sync(0xffffffffu, ss, o);
        }
        float m = s * (1.0f / 64.0f);
        float v = ss * (1.0f / 64.0f) - m * m;
        float rstd = rsqrtf(v + 1e-6f);
        int t = t0 + u0 + i;
        if (t < TN) {
            float o8[8];
            #pragma unroll
            for (int j = 0; j < 8; j++)
                o8[j] = fmaxf((a8[j] - m) * rstd * ls[j] + lb[j], 0.f);
            float* op = g_t1 + ((size_t)b * TN + t) * 64 + f0;
            *reinterpret_cast<float4*>(op) = make_float4(o8[0], o8[1], o8[2], o8[3]);
            *reinterpret_cast<float4*>(op + 4) = make_float4(o8[4], o8[5], o8[6], o8[7]);
        }
    }
}

// ---------------- conv (F->F, dilation D) + LN + relu + identity res ---------
// RES: add g_res to the input tile at load (forms t1 = t1p + res lazily).
template <int D, bool RES>
__global__ void __launch_bounds__(256, 2)
k_convres(const float* __restrict__ in,
          const float* __restrict__ resp,
          const float* __restrict__ w, const float* __restrict__ bias,
          const float* __restrict__ lns, const float* __restrict__ lnb,
          float* __restrict__ outp) {
    extern __shared__ float sm[];
    const int ROWS = 128 + 2 * D;
    float* Ts = sm;                 // ROWS x 65
    float* Ws = sm + ROWS * 65;     // 3*64*64
    int b = blockIdx.y;
    int t0 = blockIdx.x * 128;
    int tid = threadIdx.x;
    const float* inb = in + (size_t)b * TN * 64;
    const float* rsb = RES ? (resp + (size_t)b * TN * 64) : nullptr;

    for (int idx = tid; idx < ROWS * 64; idx += 256) {
        int u = idx >> 6, f = idx & 63;
        int t = t0 - D + u;
        float v = 0.f;
        if (t >= 0 && t < TN) {
            v = inb[(size_t)t * 64 + f];
            if (RES) v += rsb[(size_t)t * 64 + f];
        }
        Ts[u * 65 + f] = v;
    }
    for (int idx = tid; idx < 3 * 64 * 64; idx += 256) Ws[idx] = w[idx];
    __syncthreads();

    int tg = tid >> 3, fg = tid & 7;
    int f0 = fg * 8;
    int u0 = tg * 4;

    float ls[8], lb[8];
    ull acc[4][4];
    #pragma unroll
    for (int jj = 0; jj < 4; jj++) {
        ull bj = pk2(bias[f0 + 2 * jj], bias[f0 + 2 * jj + 1]);
        #pragma unroll
        for (int i = 0; i < 4; i++) acc[i][jj] = bj;
    }
    #pragma unroll
    for (int j = 0; j < 8; j++) { ls[j] = lns[f0 + j]; lb[j] = lnb[f0 + j]; }

    #pragma unroll 2
    for (int c = 0; c < 64; c++) {
        ull xd[2 * D + 4];
        #pragma unroll
        for (int s = 0; s < 2 * D + 4; s++) xd[s] = d2(Ts[(u0 + s) * 65 + c]);
        #pragma unroll
        for (int tap = 0; tap < 3; tap++) {
            const ull* wp = reinterpret_cast<const ull*>(&Ws[tap * 4096 + c * 64 + f0]);
            #pragma unroll
            for (int jj = 0; jj < 4; jj++) {
                ull wv = wp[jj];
                #pragma unroll
                for (int i = 0; i < 4; i++) fma2(acc[i][jj], xd[i + tap * D], wv);
            }
        }
    }

    #pragma unroll
    for (int i = 0; i < 4; i++) {
        float a8[8];
        #pragma unroll
        for (int jj = 0; jj < 4; jj++) up2(acc[i][jj], a8[2 * jj], a8[2 * jj + 1]);
        float s = 0.f, ss = 0.f;
        #pragma unroll
        for (int j = 0; j < 8; j++) { s += a8[j]; ss += a8[j] * a8[j]; }
        #pragma unroll
        for (int o = 1; o < 8; o <<= 1) {
            s  += __shfl_xor_sync(0xffffffffu, s, o);
            ss += __shfl_xor_sync(0xffffffffu, ss, o);
        }
        float m = s * (1.0f / 64.0f);
        float v = ss * (1.0f / 64.0f) - m * m;
        float rstd = rsqrtf(v + 1e-6f);
        int t = t0 + u0 + i;
        if (t < TN) {
            float o8[8];
            #pragma unroll
            for (int j = 0; j < 8; j++) {
                float h = fmaxf((a8[j] - m) * rstd * ls[j] + lb[j], 0.f);
                o8[j] = h + Ts[(u0 + i + D) * 65 + f0 + j];
            }
            float* op = outp + ((size_t)b * TN + t) * 64 + f0;
            *reinterpret_cast<float4*>(op) = make_float4(o8[0], o8[1], o8[2], o8[3]);
            *reinterpret_cast<float4*>(op + 4) = make_float4(o8[4], o8[5], o8[6], o8[7]);
        }
    }
}

// ---------------- node_feats = X @ tcn_out, K split over 2 CTAs --------------
__global__ void k_nf(const float* __restrict__ X) {
    __shared__ float Xs[128][33];
    __shared__ float Ts[32][64];
    int half = blockIdx.x;
    int b = blockIdx.y;
    int tid = threadIdx.x;
    int c0 = (tid >> 4) * 8;
    int f0 = (tid & 15) * 4;
    ull acc[8][2];
    #pragma unroll
    for (int r = 0; r < 8; r++) { acc[r][0] = 0ull; acc[r][1] = 0ull; }

    const float* Xb = X + (size_t)b * CC * TN;
    const float* Tb = g_tcn + (size_t)b * TN * 64;
    int kbeg = half * 1000, kend = kbeg + 1000;

    for (int k0 = kbeg; k0 < kend; k0 += 32) {
        for (int idx = tid; idx < 128 * 32; idx += 256) {
            int c = idx >> 5, kk = idx & 31;
            int k = k0 + kk;
            Xs[c][kk] = (k < kend) ? Xb[(size_t)c * TN + k] : 0.f;
        }
        for (int idx = tid; idx < 32 * 64; idx += 256) {
            int kk = idx >> 6, f = idx & 63;
            int k = k0 + kk;
            Ts[kk][f] = (k < kend) ? Tb[(size_t)k * 64 + f] : 0.f;
        }
        __syncthreads();
        #pragma unroll 4
        for (int kk = 0; kk < 32; kk++) {
            const ull* tp = reinterpret_cast<const ull*>(&Ts[kk][f0]);
            ull t0v = tp[0], t1v = tp[1];
            #pragma unroll
            for (int r = 0; r < 8; r++) {
                ull xd = d2(Xs[c0 + r][kk]);
                fma2(acc[r][0], xd, t0v);
                fma2(acc[r][1], xd, t1v);
            }
        }
        __syncthreads();
    }
    #pragma unroll
    for (int r = 0; r < 8; r++) {
        float v4[4];
        up2(acc[r][0], v4[0], v4[1]);
        up2(acc[r][1], v4[2], v4[3]);
        float* o = g_nf + (size_t)half * BB * CC * FF + ((size_t)b * 128 + c0 + r) * 64 + f0;
        *reinterpret_cast<float4*>(o) = make_float4(v4[0], v4[1], v4[2], v4[3]);
    }
}

// ---------------- geo = relu(LN(adj @ node_feats)) ---------------------------
__global__ void k_geo(const float* __restrict__ lns, const float* __restrict__ lnb) {
    extern __shared__ float sm[];
    float* adjs = sm;                // 128 x 129 (pad)
    float* nfs = sm + 128 * 129;     // 128 x 64
    int b = blockIdx.x, tid = threadIdx.x;   // 128 threads
    for (int idx = tid; idx < 128 * 64; idx += 128)
        nfs[idx] = g_nf[(size_t)b * 8192 + idx] + g_nf[(size_t)BB * 8192 + (size_t)b * 8192 + idx];
    {
        const float* src = g_adj + (size_t)b * 16384;
        for (int idx = tid; idx < 16384; idx += 128) {
            int i = idx >> 7, j = idx & 127;
            adjs[i * 129 + j] = src[idx];
        }
    }
    __syncthreads();

    const float* arow = adjs + tid * 129;
    ull acc[32];
    #pragma unroll
    for (int q = 0; q < 32; q++) acc[q] = 0ull;
    #pragma unroll 2
    for (int j = 0; j < 128; j++) {
        ull a = d2(arow[j]);
        const ull* n2 = reinterpret_cast<const ull*>(&nfs[j * 64]);
        #pragma unroll
        for (int q = 0; q < 32; q++) fma2(acc[q], a, n2[q]);
    }
    float av[64];
    #pragma unroll
    for (int q = 0; q < 32; q++) up2(acc[q], av[2 * q], av[2 * q + 1]);
    float s = 0.f, ss = 0.f;
    #pragma unroll
    for (int j = 0; j < 64; j++) { s += av[j]; ss += av[j] * av[j]; }
    float m = s * (1.0f / 64.0f);
    float v = ss * (1.0f / 64.0f) - m * m;
    float rstd = rsqrtf(v + 1e-6f);
    float* o = g_geo + ((size_t)b * 128 + tid) * 64;
    #pragma unroll
    for (int j = 0; j < 64; j++)
        o[j] = fmaxf((av[j] - m) * rstd * lns[j] + lnb[j], 0.f);
}

// ---------------- decay GEMV partials: 4 K-chunks per batch row --------------
__global__ void k_decay(const float* __restrict__ dw) {
    __shared__ float gs[2048];
    int part = blockIdx.x, b = blockIdx.y;
    int tid = threadIdx.x;  // 128 threads
    int kbeg = part * 2048;
    for (int idx = tid; idx < 2048; idx += 128)
        gs[idx] = g_geo[(size_t)b * 8192 + kbeg + idx];
    __syncthreads();
    float a0 = 0.f, a1 = 0.f, a2 = 0.f, a3 = 0.f;
    for (int k = 0; k < 2048; k += 4) {
        a0 += gs[k + 0] * dw[(size_t)(kbeg + k + 0) * 128 + tid];
        a1 += gs[k + 1] * dw[(size_t)(kbeg + k + 1) * 128 + tid];
        a2 += gs[k + 2] * dw[(size_t)(kbeg + k + 2) * 128 + tid];
        a3 += gs[k + 3] * dw[(size_t)(kbeg + k + 3) * 128 + tid];
    }
    g_dpart[((size_t)part * BB + b) * HH + tid] = (a0 + a1) + (a2 + a3);
}

// ---------------- chunk-mean pool of tcn + seq_w GEMM ------------------------
__global__ void k_poolseq(const float* __restrict__ sw, const float* __restrict__ sb) {
    __shared__ float ps[64];
    int s = blockIdx.x, b = blockIdx.y, tid = threadIdx.x;  // 128 threads
    if (tid < 64) {
        const float* base = g_tcn + ((size_t)b * TN + s * 200) * 64 + tid;
        float a = 0.f;
        #pragma unroll 8
        for (int t = 0; t < 200; t++) a += base[(size_t)t * 64];
        ps[tid] = a * (1.0f / 200.0f);
    }
    __syncthreads();
    float acc = sb[tid];
    #pragma unroll
    for (int f = 0; f < 64; f++) acc += ps[f] * sw[f * 128 + tid];
    g_seqin[((size_t)b * SEQN + s) * 128 + tid] = acc;
}

// ---------------- LIF scan + attention + heads -------------------------------
__global__ void k_lif(const float* __restrict__ db,
                      const float* __restrict__ aw, const float* __restrict__ ab,
                      const float* __restrict__ fw, const float* __restrict__ fb,
                      const float* __restrict__ ow, const float* __restrict__ ob,
                      float* __restrict__ dout) {
    __shared__ float red[128];
    __shared__ float attn[SEQN];
    __shared__ float featv[128];
    __shared__ float f2[64];
    int b = blockIdx.x, h = threadIdx.x;   // 128 threads

    float dacc = db[h]
        + g_dpart[((size_t)0 * BB + b) * HH + h]
        + g_dpart[((size_t)1 * BB + b) * HH + h]
        + g_dpart[((size_t)2 * BB + b) * HH + h]
        + g_dpart[((size_t)3 * BB + b) * HH + h];
    float d = 1.0f / (1.0f + expf(-dacc));

    float mem = 0.f, spsum = 0.f;
    float sp[SEQN];
    #pragma unroll
    for (int s = 0; s < SEQN; s++) {
        mem = mem * d + g_seqin[((size_t)b * SEQN + s) * 128 + h];
        float spike = (mem - 0.5f) > 0.f ? 1.0f : 0.0f;
        sp[s] = spike;
        spsum += spike;
        mem -= 0.5f * spike;
    }
    float awh = aw[h];
    for (int s = 0; s < SEQN; s++) {
        red[h] = sp[s] * awh;
        __syncthreads();
        for (int o = 64; o; o >>= 1) {
            if (h < o) red[h] += red[h + o];
            __syncthreads();
        }
        if (h == 0) attn[s] = red[0] + ab[0];
        __syncthreads();
    }
    red[h] = spsum;
    __syncthreads();
    for (int o = 64; o; o >>= 1) {
        if (h < o) red[h] += red[h + o];
        __syncthreads();
    }
    if (h == 0) atomicAdd(&g_spksum, red[0]);

    if (h == 0) {
        float mx = -1e30f;
        for (int s = 0; s < SEQN; s++) mx = fmaxf(mx, attn[s]);
        float ssum = 0.f;
        for (int s = 0; s < SEQN; s++) { attn[s] = expf(attn[s] - mx); ssum += attn[s]; }
        float inv = 1.0f / ssum;
        for (int s = 0; s < SEQN; s++) attn[s] *= inv;
    }
    __syncthreads();

    float fv = 0.f;
    #pragma unroll
    for (int s = 0; s < SEQN; s++) fv += sp[s] * attn[s];
    featv[h] = fv;
    __syncthreads();

    if (h < 64) {
        float acc = fb[h];
        for (int k = 0; k < 128; k++) acc += featv[k] * fw[k * 64 + h];
        f2[h] = fmaxf(acc, 0.f);
    }
    __syncthreads();
    if (h < 4) {
        float acc = ob[h];
        for (int j = 0; j < 64; j++) acc += f2[j] * ow[j * 4 + h];
        dout[b * 4 + h] = acc;
    }
}

__global__ void k_finmean(float* __restrict__ dout, int osz) {
    if (threadIdx.x == 0)
        dout[osz - 1] = g_spksum * (1.0f / ((float)BB * SEQN * HH));
}

// ---------------- launcher ----------------------------------------------------
extern "C" void kernel_launch(void* const* d_in, const int* in_sizes, int n_in,
                              void* d_out, int out_size) {
    const float* X    = (const float*)d_in[0];
    const float* c1w  = (const float*)d_in[1];
    const float* c1b  = (const float*)d_in[2];
    const float* l1s  = (const float*)d_in[3];
    const float* l1b  = (const float*)d_in[4];
    const float* r1w  = (const float*)d_in[5];
    const float* r1b  = (const float*)d_in[6];
    const float* c2w  = (const float*)d_in[7];
    const float* c2b  = (const float*)d_in[8];
    const float* l2s  = (const float*)d_in[9];
    const float* l2b  = (const float*)d_in[10];
    const float* c3w  = (const float*)d_in[11];
    const float* c3b  = (const float*)d_in[12];
    const float* l3s  = (const float*)d_in[13];
    const float* l3b  = (const float*)d_in[14];
    const float* lgs  = (const float*)d_in[15];
    const float* lgb  = (const float*)d_in[16];
    const float* seqw = (const float*)d_in[19];
    const float* seqb = (const float*)d_in[20];
    const float* dw   = (const float*)d_in[21];
    const float* db   = (const float*)d_in[22];
    const float* aw   = (const float*)d_in[23];
    const float* ab   = (const float*)d_in[24];
    const float* fw   = (const float*)d_in[25];
    const float* fb   = (const float*)d_in[26];
    const float* ow   = (const float*)d_in[27];
    const float* ob   = (const float*)d_in[28];
    float* out = (float*)d_out;

    float *t1p, *t2p, *tcnp, *resp;
    cudaGetSymbolAddress((void**)&t1p, g_t1);
    cudaGetSymbolAddress((void**)&t2p, g_t2);
    cudaGetSymbolAddress((void**)&tcnp, g_tcn);
    cudaGetSymbolAddress((void**)&resp, g_res);

    size_t sm_log = (size_t)2 * 128 * 128 * sizeof(float);                 // 128 KB
    size_t sm_c1  = (size_t)(128 * 258 + 3 * 128 * 64) * sizeof(float);    // 225 KB
    size_t sm_res = (size_t)(128 * 132) * sizeof(float);                   // 66 KB
    size_t sm_c2  = (size_t)(132 * 65 + 3 * 64 * 64) * sizeof(float);
    size_t sm_c3  = (size_t)(136 * 65 + 3 * 64 * 64) * sizeof(float);
    size_t sm_geo = (size_t)(128 * 129 + 128 * 64) * sizeof(float);
    cudaFuncSetAttribute(k_logadj, cudaFuncAttributeMaxDynamicSharedMemorySize, (int)sm_log);
    cudaFuncSetAttribute(k_conv1, cudaFuncAttributeMaxDynamicSharedMemorySize, (int)sm_c1);
    cudaFuncSetAttribute(k_res, cudaFuncAttributeMaxDynamicSharedMemorySize, (int)sm_res);
    cudaFuncSetAttribute(k_convres<2, true>, cudaFuncAttributeMaxDynamicSharedMemorySize, (int)sm_c2);
    cudaFuncSetAttribute(k_convres<4, false>, cudaFuncAttributeMaxDynamicSharedMemorySize, (int)sm_c3);
    cudaFuncSetAttribute(k_geo, cudaFuncAttributeMaxDynamicSharedMemorySize, (int)sm_geo);

    cudaStream_t s2 = 0;
    cudaEvent_t e1 = 0, e2 = 0, e3 = 0, e4 = 0, er = 0;
    bool fork = true;
    if (cudaStreamCreateWithFlags(&s2, cudaStreamNonBlocking) != cudaSuccess) fork = false;
    if (fork && cudaEventCreateWithFlags(&e1, cudaEventDisableTiming) != cudaSuccess) fork = false;
    if (fork && cudaEventCreateWithFlags(&e2, cudaEventDisableTiming) != cudaSuccess) fork = false;
    if (fork && cudaEventCreateWithFlags(&e3, cudaEventDisableTiming) != cudaSuccess) fork = false;
    if (fork && cudaEventCreateWithFlags(&e4, cudaEventDisableTiming) != cudaSuccess) fork = false;
    if (fork && cudaEventCreateWithFlags(&er, cudaEventDisableTiming) != cudaSuccess) fork = false;

    // anchor kernel on the origin stream (zeroes g_spksum), then fork s2
    k_zero<<<1, 32>>>();

    if (fork) {
        cudaEventRecord(e1, 0);
        cudaStreamWaitEvent(s2, e1, 0);      // joins s2 into the capture
        {   // side chain: res (consumed by cr2) then cov -> logadj
            dim3 gr(16, BB);
            k_res<<<gr, 256, sm_res, s2>>>(X, r1w, r1b);
        }
        cudaEventRecord(er, s2);
        k_cov<<<BB, 256, 0, s2>>>(X);
        k_logadj<<<BB, 256, sm_log, s2>>>();
        cudaEventRecord(e2, s2);
    } else {
        dim3 gr(16, BB);
        k_res<<<gr, 256, sm_res>>>(X, r1w, r1b);
        k_cov<<<BB, 256>>>(X);
        k_logadj<<<BB, 256, sm_log>>>();
    }

    {
        dim3 g1(8, BB);
        k_conv1<<<g1, 512, sm_c1>>>(X, c1w, c1b, l1s, l1b);
    }
    if (fork) cudaStreamWaitEvent(0, er, 0);    // res before cr2 reads it
    {
        dim3 g(16, BB);
        k_convres<2, true><<<g, 256, sm_c2>>>(t1p, resp, c2w, c2b, l2s, l2b, t2p);
        k_convres<4, false><<<g, 256, sm_c3>>>(t2p, nullptr, c3w, c3b, l3s, l3b, tcnp);
    }

    if (fork) {
        cudaEventRecord(e3, 0);          // tcn ready
        cudaStreamWaitEvent(s2, e3, 0);
        dim3 gp(SEQN, BB);
        k_poolseq<<<gp, 128, 0, s2>>>(seqw, seqb);
        cudaEventRecord(e4, s2);
    }

    {
        dim3 g(2, BB);
        k_nf<<<g, 256>>>(X);
    }
    if (!fork) {
        dim3 gp(SEQN, BB);
        k_poolseq<<<gp, 128>>>(seqw, seqb);
    }

    if (fork) cudaStreamWaitEvent(0, e2, 0);   // adj ready

    k_geo<<<BB, 128, sm_geo>>>(lgs, lgb);
    {
        dim3 g(4, BB);
        k_decay<<<g, 128>>>(dw);
    }

    if (fork) cudaStreamWaitEvent(0, e4, 0);   // seqin ready

    k_lif<<<BB, 128>>>(db, aw, ab, fw, fb, ow, ob, out);
    k_finmean<<<1, 32>>>(out, out_size);
}